// round 6
// baseline (speedup 1.0000x reference)
#include <cuda_runtime.h>

#define BATCH  64
#define NTOK   577
#define PTOK   576      // patches
#define DENS   288      // kept dense tokens
#define SSZ    288      // skipped tokens
#define GSZ    144      // selected group size
#define DIM    768
#define OUTROWS 433     // 1 + DENS + GSZ
#define RCOLS  432      // DENS + GSZ
#define EMAX   1200     // <= 4*288 = 1152 edges max

// ---------------- scratch (device globals; no allocation) ----------------
__device__ int   g_order[BATCH][PTOK];          // argsort(-cls_attn)
__device__ int   g_t2[BATCH][SSZ][2];           // top-2 neighbor per skip row
__device__ float g_Aperm[BATCH][SSZ][SSZ];      // permuted skip attention (L2-hot)
__device__ int   g_rowmap[BATCH][OUTROWS];      // attention/tk row index per output row
__device__ int   g_colmap[BATCH][RCOLS];        // attention col index per R column
__device__ int   g_ein[BATCH][EMAX];            // tk row index of edge source (alive only)
__device__ float g_ew[BATCH][EMAX];             // edge weight (alive only)
__device__ int   g_selrange[BATCH][GSZ][2];     // compacted [start,end) per selected node

// ---------------- kernel A: argsort(-cls_attn), stable ---------------------
__global__ __launch_bounds__(PTOK) void k_order(const float* __restrict__ attn) {
    const int b = blockIdx.x;
    const int p = threadIdx.x;                  // one thread per element
    __shared__ float a[PTOK];
    __shared__ int   ord[PTOK];
    a[p] = attn[(size_t)b * NTOK * PTOK + p];
    __syncthreads();
    const float v = a[p];
    int r = 0;
    const float4* a4 = (const float4*)a;
    #pragma unroll 4
    for (int q4 = 0; q4 < PTOK / 4; q4++) {
        float4 u4 = a4[q4];
        int qb = q4 * 4;
        r += (u4.x > v) || (u4.x == v && qb     < p);
        r += (u4.y > v) || (u4.y == v && qb + 1 < p);
        r += (u4.z > v) || (u4.z == v && qb + 2 < p);
        r += (u4.w > v) || (u4.w == v && qb + 3 < p);
    }
    ord[r] = p;
    __syncthreads();
    g_order[b][p] = ord[p];
}

// ------- kernel B: top-2 per skip row (1 warp per row) + Aperm write -------
__global__ __launch_bounds__(128) void k_top2(const float* __restrict__ attn) {
    const int b    = blockIdx.y;
    const int warp = threadIdx.x >> 5;
    const int lane = threadIdx.x & 31;
    const int i    = blockIdx.x * 4 + warp;     // skip row index 0..287

    __shared__ int   ords[SSZ];
    __shared__ float rows[4][PTOK];
    __shared__ float perm[4][SSZ];

    for (int j = threadIdx.x; j < SSZ; j += 128) ords[j] = g_order[b][DENS + j];
    __syncthreads();

    const int ri = 1 + ords[i];
    const float* src = attn + ((size_t)b * NTOK + ri) * PTOK;
    for (int p = lane; p < PTOK; p += 32) rows[warp][p] = src[p];
    __syncwarp();

    // gather permuted row values once; reuse for top-2 AND Aperm store
    float myv[9];
    #pragma unroll
    for (int k = 0; k < 9; k++) {
        int j = lane + k * 32;
        float v = rows[warp][ords[j]];
        myv[k] = v;
        perm[warp][j] = v;
    }

    // local top-2 with key = (monotone(value), 287-j): tie -> smaller j wins
    unsigned long long k1 = 0ull, k2 = 0ull;
    #pragma unroll
    for (int k = 0; k < 9; k++) {
        int j = lane + k * 32;
        if (j == i) continue;
        unsigned ub = __float_as_uint(myv[k]);
        ub ^= (unsigned)(((int)ub >> 31)) | 0x80000000u;   // total order on floats
        unsigned long long key = ((unsigned long long)ub << 32) | (unsigned)(SSZ - 1 - j);
        if (key > k1)      { k2 = k1; k1 = key; }
        else if (key > k2) { k2 = key; }
    }
    #pragma unroll
    for (int off = 16; off > 0; off >>= 1) {
        unsigned long long o1 = __shfl_down_sync(0xffffffffu, k1, off);
        unsigned long long o2 = __shfl_down_sync(0xffffffffu, k2, off);
        if (o1 > k1) { k2 = (k1 > o2) ? k1 : o2; k1 = o1; }
        else         { k2 = (k2 > o1) ? k2 : o1; }
    }
    if (lane == 0) {
        g_t2[b][i][0] = SSZ - 1 - (int)(k1 & 0xffffffffu);
        g_t2[b][i][1] = SSZ - 1 - (int)(k2 & 0xffffffffu);
    }
    __syncwarp();
    // coalesced Aperm row write (keep in L2: normal stores)
    for (int p = lane; p < SSZ; p += 32) g_Aperm[b][i][p] = perm[warp][p];
}

// ---- parallel exclusive scan over 288 per-thread values (288 threads) -----
__device__ __forceinline__ void scan288(int tid, int v, int* offs, int* wsum) {
    const int lane = tid & 31, warp = tid >> 5;     // 9 warps
    int incl = v;
    #pragma unroll
    for (int off = 1; off < 32; off <<= 1) {
        int n = __shfl_up_sync(0xffffffffu, incl, off);
        if (lane >= off) incl += n;
    }
    if (lane == 31) wsum[warp] = incl;
    __syncthreads();
    if (tid == 0) {
        int acc = 0;
        #pragma unroll
        for (int w = 0; w < 9; w++) { int t = wsum[w]; wsum[w] = acc; acc += t; }
        offs[SSZ] = acc;
    }
    __syncthreads();
    offs[tid] = incl - v + wsum[warp];
    __syncthreads();
}

// ---------------- kernel C: symmetrize + CSR + prune + select --------------
__global__ __launch_bounds__(288) void k_graph2() {
    const int b   = blockIdx.x;
    const int tid = threadIdx.x;                 // 288 threads

    __shared__ int   order[PTOK];
    __shared__ unsigned colbits[SSZ * 9];        // bit i of colbits[j*9+(i>>5)] = edge i->j
    __shared__ int   offs[SSZ + 1];
    __shared__ int   coffs[SSZ + 1];
    __shared__ int   ein[EMAX];
    __shared__ float ew[EMAX];
    __shared__ unsigned char alive[EMAX];
    __shared__ float favg[SSZ];
    __shared__ int   degi[SSZ];
    __shared__ int   gsel[GSZ];
    __shared__ int   wsum[9];
    __shared__ int   changed;

    for (int p = tid; p < PTOK; p += 288) order[p] = g_order[b][p];
    for (int k = tid; k < SSZ * 9; k += 288) colbits[k] = 0;
    __syncthreads();

    // symmetrize (column-major bit store)
    {
        const int i = tid;
        const int j1 = g_t2[b][i][0], j2 = g_t2[b][i][1];
        atomicOr(&colbits[j1 * 9 + (i >> 5)], 1u << (i & 31));   // i -> j1
        atomicOr(&colbits[j2 * 9 + (i >> 5)], 1u << (i & 31));   // i -> j2
        atomicOr(&colbits[i * 9 + (j1 >> 5)], 1u << (j1 & 31));  // j1 -> i
        atomicOr(&colbits[i * 9 + (j2 >> 5)], 1u << (j2 & 31));  // j2 -> i
    }
    __syncthreads();

    // per-column in-degree via popcount, then exclusive scan
    int mycnt = 0;
    #pragma unroll
    for (int w = 0; w < 9; w++) mycnt += __popc(colbits[tid * 9 + w]);
    scan288(tid, mycnt, offs, wsum);

    // fill incoming CSR (i ascending within each j) via ffs walk; weights from
    // the L2-resident permuted matrix. M = (W != 0)
    {
        const int j = tid;
        int ptr = offs[j];
        #pragma unroll
        for (int w = 0; w < 9; w++) {
            unsigned m = colbits[j * 9 + w];
            while (m) {
                int i = w * 32 + __ffs(m) - 1;
                m &= m - 1;
                float wv = g_Aperm[b][i][j];
                ein[ptr] = i;
                ew[ptr]  = wv;
                alive[ptr] = (wv != 0.f) ? 1 : 0;
                ptr++;
            }
        }
    }

    // fixed-point pruning: m <- m & (avg[j] > avg[i])
    for (;;) {
        __syncthreads();
        {
            const int j = tid;
            int dg = 0; float s = 0.f;
            for (int e = offs[j]; e < offs[j + 1]; e++)
                if (alive[e]) { dg++; s += ew[e]; }
            degi[j] = dg;
            favg[j] = (dg > 0) ? (s / (float)dg) : 0.f;
        }
        if (tid == 0) changed = 0;
        __syncthreads();
        {
            const int j = tid;
            const float aj = favg[j];
            int ch = 0;
            for (int e = offs[j]; e < offs[j + 1]; e++)
                if (alive[e] && !(aj > favg[ein[e]])) { alive[e] = 0; ch = 1; }
            if (ch) atomicExch(&changed, 1);
        }
        __syncthreads();
        if (!changed) break;
    }
    // degi[j] == final alive in-degree

    // compacted offsets over final degrees
    scan288(tid, degi[tid], coffs, wsum);

    // top-144 by in-degree (ties -> smaller index first)
    {
        const int j = tid;
        const int dj = degi[j];
        int r = 0;
        for (int q = 0; q < SSZ; q++) {
            int dq = degi[q];
            r += (dq > dj) || (dq == dj && q < j);
        }
        if (r < GSZ) gsel[r] = j;
    }

    // compacted alive edges to global (tk-row-resolved)
    {
        const int j = tid;
        int ptr = coffs[j];
        for (int e = offs[j]; e < offs[j + 1]; e++) {
            if (alive[e]) {
                g_ein[b][ptr] = 1 + order[DENS + ein[e]];
                g_ew[b][ptr]  = ew[e];
                ptr++;
            }
        }
    }
    __syncthreads();

    for (int g = tid; g < GSZ; g += 288) {
        int j = gsel[g];
        g_selrange[b][g][0] = coffs[j];
        g_selrange[b][g][1] = coffs[j] + degi[j];
    }
    for (int u = tid; u < OUTROWS; u += 288) {
        int row;
        if (u == 0)            row = 0;
        else if (u <= DENS)    row = 1 + order[u - 1];
        else                   row = 1 + order[DENS + gsel[u - 1 - DENS]];
        g_rowmap[b][u] = row;
    }
    for (int v = tid; v < RCOLS; v += 288) {
        int c;
        if (v < DENS) c = order[v];
        else          c = order[DENS + gsel[v - DENS]];
        g_colmap[b][v] = c;
    }
}

// ---- dense output (order-only): token rows 0..288 + R cols 0..287 ---------
__global__ __launch_bounds__(192) void k_dense(const float* __restrict__ tk,
                                               const float* __restrict__ attn,
                                               float* __restrict__ out) {
    __shared__ float srow[PTOK];
    __shared__ int   cm[DENS];
    const int u = blockIdx.x;                    // 0..288
    const int b = blockIdx.y;
    const int t = threadIdx.x;                   // 192
    const int row = (u == 0) ? 0 : 1 + g_order[b][u - 1];

    const float4* a4 = (const float4*)(attn + ((size_t)b * NTOK + row) * PTOK);
    if (t < PTOK / 4) ((float4*)srow)[t] = a4[t];
    for (int v2 = t; v2 < DENS; v2 += 192) cm[v2] = g_order[b][v2];

    const float4* tk4 = (const float4*)tk;
    float4 v = tk4[((size_t)b * NTOK + row) * (DIM / 4) + t];
    __stcs(((float4*)out) + ((size_t)b * OUTROWS + u) * (DIM / 4) + t, v);

    __syncthreads();
    float* dst = out + (size_t)BATCH * OUTROWS * DIM
                     + ((size_t)b * OUTROWS + u) * RCOLS;
    for (int v2 = t; v2 < DENS; v2 += 192) __stcs(dst + v2, srow[cm[v2]]);
}

// ---- rest (needs full graph): agg rows full; dense rows' last 144 R cols --
__global__ __launch_bounds__(192) void k_rest(const float* __restrict__ tk,
                                              const float* __restrict__ attn,
                                              float* __restrict__ out) {
    __shared__ float srow[PTOK];
    __shared__ int   cmap[RCOLS];
    const int u = blockIdx.x;                    // 0..432
    const int b = blockIdx.y;
    const int t = threadIdx.x;                   // 192
    float* outR = out + (size_t)BATCH * OUTROWS * DIM;

    if (u <= DENS) {
        // stage full attention row coalesced, emit only R cols 288..431
        const int row = (u == 0) ? 0 : 1 + g_order[b][u - 1];
        const float4* a4 = (const float4*)(attn + ((size_t)b * NTOK + row) * PTOK);
        if (t < PTOK / 4) ((float4*)srow)[t] = a4[t];
        if (t < GSZ) cmap[t] = g_colmap[b][DENS + t];
        __syncthreads();
        float* dst = outR + ((size_t)b * OUTROWS + u) * RCOLS;
        if (t < GSZ) __stcs(dst + DENS + t, srow[cmap[t]]);
        return;
    }

    // aggregated row: full tokens row + full R row
    const int g   = u - 1 - DENS;
    const int row = g_rowmap[b][u];
    const int st  = g_selrange[b][g][0];
    const int en  = g_selrange[b][g][1];

    const float4* a4 = (const float4*)(attn + ((size_t)b * NTOK + row) * PTOK);
    if (t < PTOK / 4) ((float4*)srow)[t] = a4[t];
    for (int v2 = t; v2 < RCOLS; v2 += 192) cmap[v2] = g_colmap[b][v2];

    const float4* tk4 = (const float4*)tk;
    float4 v = tk4[((size_t)b * NTOK + row) * (DIM / 4) + t];
    float4 acc = make_float4(0.f, 0.f, 0.f, 0.f);
    for (int e = st; e < en; e++) {              // alive-only, ascending i
        float w  = g_ew[b][e];
        int   sr = g_ein[b][e];
        float4 sv = tk4[((size_t)b * NTOK + sr) * (DIM / 4) + t];
        acc.x += w * sv.x; acc.y += w * sv.y;
        acc.z += w * sv.z; acc.w += w * sv.w;
    }
    v.x = acc.x + v.x; v.y = acc.y + v.y;
    v.z = acc.z + v.z; v.w = acc.w + v.w;
    __stcs(((float4*)out) + ((size_t)b * OUTROWS + u) * (DIM / 4) + t, v);

    __syncthreads();
    float* dst = outR + ((size_t)b * OUTROWS + u) * RCOLS;
    for (int v2 = t; v2 < RCOLS; v2 += 192) __stcs(dst + v2, srow[cmap[v2]]);
}

// ---------------- launch ---------------------------------------------------
extern "C" void kernel_launch(void* const* d_in, const int* in_sizes, int n_in,
                              void* d_out, int out_size) {
    const float* tk   = (const float*)d_in[0];
    const float* attn = (const float*)d_in[1];
    float* out = (float*)d_out;

    static cudaStream_t s2 = nullptr;
    static cudaEvent_t  evA = nullptr, evB = nullptr;
    if (s2 == nullptr) {                         // first call is outside capture
        cudaStreamCreateWithFlags(&s2, cudaStreamNonBlocking);
        cudaEventCreateWithFlags(&evA, cudaEventDisableTiming);
        cudaEventCreateWithFlags(&evB, cudaEventDisableTiming);
    }

    k_order <<<BATCH, PTOK>>>(attn);
    cudaEventRecord(evA, 0);                     // fork after order
    cudaStreamWaitEvent(s2, evA, 0);
    k_dense <<<dim3(DENS + 1, BATCH), 192, 0, s2>>>(tk, attn, out);
    cudaEventRecord(evB, s2);

    k_top2  <<<dim3(SSZ / 4, BATCH), 128>>>(attn);
    k_graph2<<<BATCH, 288>>>();
    cudaStreamWaitEvent(0, evB, 0);              // join
    k_rest  <<<dim3(OUTROWS, BATCH), 192>>>(tk, attn, out);
}

// round 7
// speedup vs baseline: 1.2377x; 1.2377x over previous
#include <cuda_runtime.h>

#define BATCH  64
#define NTOK   577
#define PTOK   576      // patches
#define DENS   288      // kept dense tokens
#define SSZ    288      // skipped tokens
#define GSZ    144      // selected group size
#define DIM    768
#define OUTROWS 433     // 1 + DENS + GSZ
#define RCOLS  432      // DENS + GSZ
#define EMAX   1200     // <= 4*288 = 1152 edges max

// ---------------- scratch (device globals; no allocation) ----------------
__device__ int   g_order[BATCH][PTOK];          // argsort(-cls_attn)
__device__ int   g_t2[BATCH][SSZ][2];           // top-2 neighbor per skip row
__device__ int   g_rowmap[BATCH][OUTROWS];      // attention/tk row index per output row
__device__ int   g_colmap[BATCH][RCOLS];        // attention col index per R column
__device__ int   g_ein[BATCH][EMAX];            // tk row index of edge source (alive only)
__device__ float g_ew[BATCH][EMAX];             // edge weight (alive only)
__device__ int   g_selrange[BATCH][GSZ][2];     // compacted [start,end) per selected node

// ---------------- kernel A: argsort(-cls_attn), stable ---------------------
__global__ __launch_bounds__(PTOK) void k_order(const float* __restrict__ attn) {
    const int b = blockIdx.x;
    const int p = threadIdx.x;                  // one thread per element
    __shared__ float a[PTOK];
    __shared__ int   ord[PTOK];
    a[p] = attn[(size_t)b * NTOK * PTOK + p];
    __syncthreads();
    const float v = a[p];
    int r = 0;
    const float4* a4 = (const float4*)a;
    #pragma unroll 4
    for (int q4 = 0; q4 < PTOK / 4; q4++) {
        float4 u4 = a4[q4];
        int qb = q4 * 4;
        r += (u4.x > v) || (u4.x == v && qb     < p);
        r += (u4.y > v) || (u4.y == v && qb + 1 < p);
        r += (u4.z > v) || (u4.z == v && qb + 2 < p);
        r += (u4.w > v) || (u4.w == v && qb + 3 < p);
    }
    ord[r] = p;
    __syncthreads();
    g_order[b][p] = ord[p];
}

// ---------------- kernel B: top-2 per skip row (1 warp per row) ------------
__global__ __launch_bounds__(128) void k_top2(const float* __restrict__ attn) {
    const int b    = blockIdx.y;
    const int warp = threadIdx.x >> 5;
    const int lane = threadIdx.x & 31;
    const int i    = blockIdx.x * 4 + warp;     // skip row index 0..287

    __shared__ int   ords[SSZ];
    __shared__ float rows[4][PTOK];

    for (int j = threadIdx.x; j < SSZ; j += 128) ords[j] = g_order[b][DENS + j];
    __syncthreads();

    const int ri = 1 + ords[i];
    const float* src = attn + ((size_t)b * NTOK + ri) * PTOK;
    for (int p = lane; p < PTOK; p += 32) rows[warp][p] = src[p];
    __syncwarp();

    // local top-2 with key = (monotone(value), 287-j): tie -> smaller j wins
    unsigned long long k1 = 0ull, k2 = 0ull;
    #pragma unroll
    for (int k = 0; k < 9; k++) {
        int j = lane + k * 32;
        if (j == i) continue;
        float v = rows[warp][ords[j]];
        unsigned ub = __float_as_uint(v);
        ub ^= (unsigned)(((int)ub >> 31)) | 0x80000000u;   // total order on floats
        unsigned long long key = ((unsigned long long)ub << 32) | (unsigned)(SSZ - 1 - j);
        if (key > k1)      { k2 = k1; k1 = key; }
        else if (key > k2) { k2 = key; }
    }
    #pragma unroll
    for (int off = 16; off > 0; off >>= 1) {
        unsigned long long o1 = __shfl_down_sync(0xffffffffu, k1, off);
        unsigned long long o2 = __shfl_down_sync(0xffffffffu, k2, off);
        if (o1 > k1) { k2 = (k1 > o2) ? k1 : o2; k1 = o1; }
        else         { k2 = (k2 > o1) ? k2 : o1; }
    }
    if (lane == 0) {
        g_t2[b][i][0] = SSZ - 1 - (int)(k1 & 0xffffffffu);
        g_t2[b][i][1] = SSZ - 1 - (int)(k2 & 0xffffffffu);
    }
}

// ---- parallel exclusive scan over 288 per-thread values (288 threads) -----
__device__ __forceinline__ void scan288(int tid, int v, int* offs, int* wsum) {
    const int lane = tid & 31, warp = tid >> 5;     // 9 warps
    int incl = v;
    #pragma unroll
    for (int off = 1; off < 32; off <<= 1) {
        int n = __shfl_up_sync(0xffffffffu, incl, off);
        if (lane >= off) incl += n;
    }
    if (lane == 31) wsum[warp] = incl;
    __syncthreads();
    if (tid == 0) {
        int acc = 0;
        #pragma unroll
        for (int w = 0; w < 9; w++) { int t = wsum[w]; wsum[w] = acc; acc += t; }
        offs[SSZ] = acc;
    }
    __syncthreads();
    offs[tid] = incl - v + wsum[warp];
    __syncthreads();
}

// ---------------- kernel C: symmetrize + CSR + prune + select --------------
__global__ __launch_bounds__(288) void k_graph2(const float* __restrict__ attn) {
    const int b   = blockIdx.x;
    const int tid = threadIdx.x;                 // 288 threads
    const float* A0 = attn + (size_t)b * NTOK * PTOK;

    __shared__ int   order[PTOK];
    __shared__ unsigned colbits[SSZ * 9];        // bit i of colbits[j*9+(i>>5)] = edge i->j
    __shared__ int   offs[SSZ + 1];
    __shared__ int   coffs[SSZ + 1];
    __shared__ int   ein[EMAX];
    __shared__ float ew[EMAX];
    __shared__ unsigned char alive[EMAX];
    __shared__ float favg[2][SSZ];               // double-buffered averages
    __shared__ int   degi[SSZ];
    __shared__ int   gsel[GSZ];
    __shared__ int   wsum[9];

    for (int p = tid; p < PTOK; p += 288) order[p] = g_order[b][p];
    for (int k = tid; k < SSZ * 9; k += 288) colbits[k] = 0;
    __syncthreads();

    // symmetrize (column-major bit store)
    {
        const int i = tid;
        const int j1 = g_t2[b][i][0], j2 = g_t2[b][i][1];
        atomicOr(&colbits[j1 * 9 + (i >> 5)], 1u << (i & 31));   // i -> j1
        atomicOr(&colbits[j2 * 9 + (i >> 5)], 1u << (i & 31));   // i -> j2
        atomicOr(&colbits[i * 9 + (j1 >> 5)], 1u << (j1 & 31));  // j1 -> i
        atomicOr(&colbits[i * 9 + (j2 >> 5)], 1u << (j2 & 31));  // j2 -> i
    }
    __syncthreads();

    // per-column in-degree via popcount, then exclusive scan
    int mycnt = 0;
    #pragma unroll
    for (int w = 0; w < 9; w++) mycnt += __popc(colbits[tid * 9 + w]);
    scan288(tid, mycnt, offs, wsum);

    const int j   = tid;
    const int st0 = offs[j], en0 = offs[j + 1];

    // fill incoming CSR (i ascending within each j) via ffs walk. M = (W != 0)
    {
        const int cj = order[DENS + j];
        int ptr = st0;
        #pragma unroll
        for (int w = 0; w < 9; w++) {
            unsigned m = colbits[j * 9 + w];
            while (m) {
                int i = w * 32 + __ffs(m) - 1;
                m &= m - 1;
                float wv = A0[(size_t)(1 + order[DENS + i]) * PTOK + cj];
                ein[ptr] = i;
                ew[ptr]  = wv;
                alive[ptr] = (wv != 0.f) ? 1 : 0;
                ptr++;
            }
        }
    }

    // initial averages (own column only -> no barrier needed yet)
    int cur = 0;
    {
        int dg = 0; float s = 0.f;
        for (int e = st0; e < en0; e++)
            if (alive[e]) { dg++; s += ew[e]; }
        degi[j] = dg;
        favg[0][j] = (dg > 0) ? (s / (float)dg) : 0.f;
    }
    __syncthreads();                             // favg[0] visible to all

    // fixed point: ONE barrier-op per iteration (syncthreads_or carries both
    // the convergence reduction and the favg[nxt] publication).
    for (;;) {
        const float aj = favg[cur][j];
        int ch = 0;
        for (int e = st0; e < en0; e++)
            if (alive[e] && !(aj > favg[cur][ein[e]])) { alive[e] = 0; ch = 1; }
        int dg = 0; float s = 0.f;
        for (int e = st0; e < en0; e++)
            if (alive[e]) { dg++; s += ew[e]; }
        degi[j] = dg;
        favg[cur ^ 1][j] = (dg > 0) ? (s / (float)dg) : 0.f;
        if (!__syncthreads_or(ch)) break;
        cur ^= 1;
    }
    // degi[j] == final alive in-degree

    // compacted offsets over final degrees
    scan288(tid, degi[tid], coffs, wsum);

    // top-144 by in-degree (ties -> smaller index first)
    {
        const int dj = degi[j];
        int r = 0;
        for (int q = 0; q < SSZ; q++) {
            int dq = degi[q];
            r += (dq > dj) || (dq == dj && q < j);
        }
        if (r < GSZ) gsel[r] = j;
    }

    // compacted alive edges to global (tk-row-resolved)
    {
        int ptr = coffs[j];
        for (int e = st0; e < en0; e++) {
            if (alive[e]) {
                g_ein[b][ptr] = 1 + order[DENS + ein[e]];
                g_ew[b][ptr]  = ew[e];
                ptr++;
            }
        }
    }
    __syncthreads();

    for (int g = tid; g < GSZ; g += 288) {
        int jj = gsel[g];
        g_selrange[b][g][0] = coffs[jj];
        g_selrange[b][g][1] = coffs[jj] + degi[jj];
    }
    for (int u = tid; u < OUTROWS; u += 288) {
        int row;
        if (u == 0)            row = 0;
        else if (u <= DENS)    row = 1 + order[u - 1];
        else                   row = 1 + order[DENS + gsel[u - 1 - DENS]];
        g_rowmap[b][u] = row;
    }
    for (int v = tid; v < RCOLS; v += 288) {
        int c;
        if (v < DENS) c = order[v];
        else          c = order[DENS + gsel[v - DENS]];
        g_colmap[b][v] = c;
    }
}

// -------- fused output kernel: out_tokens [B,433,768] + R [B,433,432] ------
__global__ __launch_bounds__(192) void k_out(const float* __restrict__ tk,
                                             const float* __restrict__ attn,
                                             float* __restrict__ out) {
    __shared__ float srow[PTOK];
    __shared__ int   cmap[RCOLS];
    const int u = blockIdx.x;
    const int b = blockIdx.y;
    const int t = threadIdx.x;                   // 192 threads
    const int row = g_rowmap[b][u];

    // stage attention row (float4) + column map early
    const float4* a4 = (const float4*)(attn + ((size_t)b * NTOK + row) * PTOK);
    if (t < PTOK / 4) ((float4*)srow)[t] = a4[t];
    for (int v2 = t; v2 < RCOLS; v2 += 192) cmap[v2] = g_colmap[b][v2];

    // ---- tokens: one float4 per thread ----
    const float4* tk4 = (const float4*)tk;
    float4 v = tk4[((size_t)b * NTOK + row) * (DIM / 4) + t];
    if (u > DENS) {                              // aggregated skip-selected rows
        const int g = u - 1 - DENS;
        const int st = g_selrange[b][g][0];
        const int en = g_selrange[b][g][1];
        float4 acc = make_float4(0.f, 0.f, 0.f, 0.f);
        for (int e = st; e < en; e++) {          // alive-only, branch-free body
            float w  = g_ew[b][e];
            int   sr = g_ein[b][e];
            float4 sv = tk4[((size_t)b * NTOK + sr) * (DIM / 4) + t];
            acc.x += w * sv.x; acc.y += w * sv.y;
            acc.z += w * sv.z; acc.w += w * sv.w;
        }
        v.x = acc.x + v.x; v.y = acc.y + v.y;
        v.z = acc.z + v.z; v.w = acc.w + v.w;
    }
    __stcs(((float4*)out) + ((size_t)b * OUTROWS + u) * (DIM / 4) + t, v);

    // ---- R row ----
    __syncthreads();
    float* dst = out + (size_t)BATCH * OUTROWS * DIM
                     + ((size_t)b * OUTROWS + u) * RCOLS;
    for (int v2 = t; v2 < RCOLS; v2 += 192) __stcs(dst + v2, srow[cmap[v2]]);
}

// ---------------- launch ---------------------------------------------------
extern "C" void kernel_launch(void* const* d_in, const int* in_sizes, int n_in,
                              void* d_out, int out_size) {
    const float* tk   = (const float*)d_in[0];
    const float* attn = (const float*)d_in[1];
    float* out = (float*)d_out;

    k_order <<<BATCH, PTOK>>>(attn);
    k_top2  <<<dim3(SSZ / 4, BATCH), 128>>>(attn);
    k_graph2<<<BATCH, 288>>>(attn);
    k_out   <<<dim3(OUTROWS, BATCH), 192>>>(tk, attn, out);
}

// round 8
// speedup vs baseline: 1.2414x; 1.0030x over previous
#include <cuda_runtime.h>

#define BATCH  64
#define NTOK   577
#define PTOK   576      // patches
#define DENS   288      // kept dense tokens
#define SSZ    288      // skipped tokens
#define GSZ    144      // selected group size
#define DIM    768
#define OUTROWS 433     // 1 + DENS + GSZ
#define RCOLS  432      // DENS + GSZ
#define EMAX   1200     // <= 4*288 = 1152 edges max

// ---------------- scratch (device globals; no allocation) ----------------
__device__ int   g_order[BATCH][PTOK];          // argsort(-cls_attn)
__device__ int   g_t2[BATCH][SSZ][2];           // top-2 neighbor per skip row
__device__ int   g_rowmap[BATCH][OUTROWS];      // attention/tk row index per output row
__device__ int   g_colmap[BATCH][RCOLS];        // attention col index per R column
__device__ int   g_ein[BATCH][EMAX];            // tk row index of edge source (alive only)
__device__ float g_ew[BATCH][EMAX];             // edge weight (alive only)
__device__ int   g_selrange[BATCH][GSZ][2];     // compacted [start,end) per selected node

// ---------------- kernel A: argsort(-cls_attn), stable, 4 segs/batch -------
__global__ __launch_bounds__(192) void k_order(const float* __restrict__ attn) {
    const int b   = blockIdx.y;
    const int seg = blockIdx.x;                 // 0..3 -> elements seg*144..+143
    __shared__ float a[PTOK];
    for (int p = threadIdx.x; p < PTOK; p += 192)
        a[p] = attn[(size_t)b * NTOK * PTOK + p];
    __syncthreads();
    if (threadIdx.x < 144) {
        const int p = seg * 144 + threadIdx.x;
        const float v = a[p];
        int r = 0;
        const float4* a4 = (const float4*)a;
        #pragma unroll 4
        for (int q4 = 0; q4 < PTOK / 4; q4++) {
            float4 u4 = a4[q4];
            int qb = q4 * 4;
            r += (u4.x > v) || (u4.x == v && qb     < p);
            r += (u4.y > v) || (u4.y == v && qb + 1 < p);
            r += (u4.z > v) || (u4.z == v && qb + 2 < p);
            r += (u4.w > v) || (u4.w == v && qb + 3 < p);
        }
        g_order[b][r] = p;                      // ranks are unique -> disjoint
    }
}

// ---------------- kernel B: top-2 per skip row (1 warp per row) ------------
__global__ __launch_bounds__(256) void k_top2(const float* __restrict__ attn) {
    const int b    = blockIdx.y;
    const int warp = threadIdx.x >> 5;          // 8 warps
    const int lane = threadIdx.x & 31;
    const int i    = blockIdx.x * 8 + warp;     // skip row index 0..287

    __shared__ int   ords[SSZ];
    __shared__ float rows[8][PTOK];

    for (int j = threadIdx.x; j < SSZ; j += 256) ords[j] = g_order[b][DENS + j];
    __syncthreads();

    const int ri = 1 + ords[i];
    const float* src = attn + ((size_t)b * NTOK + ri) * PTOK;
    for (int p = lane; p < PTOK; p += 32) rows[warp][p] = src[p];
    __syncwarp();

    // local top-2 with key = (monotone(value), 287-j): tie -> smaller j wins
    unsigned long long k1 = 0ull, k2 = 0ull;
    #pragma unroll
    for (int k = 0; k < 9; k++) {
        int j = lane + k * 32;
        if (j == i) continue;
        float v = rows[warp][ords[j]];
        unsigned ub = __float_as_uint(v);
        ub ^= (unsigned)(((int)ub >> 31)) | 0x80000000u;   // total order on floats
        unsigned long long key = ((unsigned long long)ub << 32) | (unsigned)(SSZ - 1 - j);
        if (key > k1)      { k2 = k1; k1 = key; }
        else if (key > k2) { k2 = key; }
    }
    #pragma unroll
    for (int off = 16; off > 0; off >>= 1) {
        unsigned long long o1 = __shfl_down_sync(0xffffffffu, k1, off);
        unsigned long long o2 = __shfl_down_sync(0xffffffffu, k2, off);
        if (o1 > k1) { k2 = (k1 > o2) ? k1 : o2; k1 = o1; }
        else         { k2 = (k2 > o1) ? k2 : o1; }
    }
    if (lane == 0) {
        g_t2[b][i][0] = SSZ - 1 - (int)(k1 & 0xffffffffu);
        g_t2[b][i][1] = SSZ - 1 - (int)(k2 & 0xffffffffu);
    }
}

// ---- parallel exclusive scan over 288 per-thread values (288 threads) -----
__device__ __forceinline__ void scan288(int tid, int v, int* offs, int* wsum) {
    const int lane = tid & 31, warp = tid >> 5;     // 9 warps
    int incl = v;
    #pragma unroll
    for (int off = 1; off < 32; off <<= 1) {
        int n = __shfl_up_sync(0xffffffffu, incl, off);
        if (lane >= off) incl += n;
    }
    if (lane == 31) wsum[warp] = incl;
    __syncthreads();
    if (tid == 0) {
        int acc = 0;
        #pragma unroll
        for (int w = 0; w < 9; w++) { int t = wsum[w]; wsum[w] = acc; acc += t; }
        offs[SSZ] = acc;
    }
    __syncthreads();
    offs[tid] = incl - v + wsum[warp];
    __syncthreads();
}

// ---------------- kernel C: symmetrize + CSR + prune + select --------------
__global__ __launch_bounds__(288) void k_graph2(const float* __restrict__ attn) {
    const int b   = blockIdx.x;
    const int tid = threadIdx.x;                 // 288 threads
    const float* A0 = attn + (size_t)b * NTOK * PTOK;

    __shared__ int   order[PTOK];
    __shared__ unsigned colbits[SSZ * 9];        // bit i of colbits[j*9+(i>>5)] = edge i->j
    __shared__ int   offs[SSZ + 1];
    __shared__ int   coffs[SSZ + 1];
    __shared__ int   ein[EMAX];
    __shared__ float ew[EMAX];
    __shared__ unsigned char alive[EMAX];
    __shared__ float favg[2][SSZ];               // double-buffered averages
    __shared__ int   degi[SSZ];
    __shared__ int   gsel[GSZ];
    __shared__ int   wsum[9];

    for (int p = tid; p < PTOK; p += 288) order[p] = g_order[b][p];
    for (int k = tid; k < SSZ * 9; k += 288) colbits[k] = 0;
    __syncthreads();

    // symmetrize (column-major bit store)
    {
        const int i = tid;
        const int j1 = g_t2[b][i][0], j2 = g_t2[b][i][1];
        atomicOr(&colbits[j1 * 9 + (i >> 5)], 1u << (i & 31));   // i -> j1
        atomicOr(&colbits[j2 * 9 + (i >> 5)], 1u << (i & 31));   // i -> j2
        atomicOr(&colbits[i * 9 + (j1 >> 5)], 1u << (j1 & 31));  // j1 -> i
        atomicOr(&colbits[i * 9 + (j2 >> 5)], 1u << (j2 & 31));  // j2 -> i
    }
    __syncthreads();

    // per-column in-degree via popcount, then exclusive scan
    int mycnt = 0;
    #pragma unroll
    for (int w = 0; w < 9; w++) mycnt += __popc(colbits[tid * 9 + w]);
    scan288(tid, mycnt, offs, wsum);

    const int j   = tid;
    const int st0 = offs[j], en0 = offs[j + 1];

    // fill incoming CSR (i ascending within each j) via ffs walk. M = (W != 0)
    {
        const int cj = order[DENS + j];
        int ptr = st0;
        #pragma unroll
        for (int w = 0; w < 9; w++) {
            unsigned m = colbits[j * 9 + w];
            while (m) {
                int i = w * 32 + __ffs(m) - 1;
                m &= m - 1;
                float wv = A0[(size_t)(1 + order[DENS + i]) * PTOK + cj];
                ein[ptr] = i;
                ew[ptr]  = wv;
                alive[ptr] = (wv != 0.f) ? 1 : 0;
                ptr++;
            }
        }
    }

    // initial averages (own column only -> no barrier needed yet)
    int cur = 0;
    {
        int dg = 0; float s = 0.f;
        for (int e = st0; e < en0; e++)
            if (alive[e]) { dg++; s += ew[e]; }
        degi[j] = dg;
        favg[0][j] = (dg > 0) ? (s / (float)dg) : 0.f;
    }
    __syncthreads();                             // favg[0] visible to all

    // fixed point: ONE barrier-op per iteration
    for (;;) {
        const float aj = favg[cur][j];
        int ch = 0;
        for (int e = st0; e < en0; e++)
            if (alive[e] && !(aj > favg[cur][ein[e]])) { alive[e] = 0; ch = 1; }
        int dg = 0; float s = 0.f;
        for (int e = st0; e < en0; e++)
            if (alive[e]) { dg++; s += ew[e]; }
        degi[j] = dg;
        favg[cur ^ 1][j] = (dg > 0) ? (s / (float)dg) : 0.f;
        if (!__syncthreads_or(ch)) break;
        cur ^= 1;
    }
    // degi[j] == final alive in-degree

    // compacted offsets over final degrees
    scan288(tid, degi[tid], coffs, wsum);

    // top-144 by in-degree (ties -> smaller index first)
    {
        const int dj = degi[j];
        int r = 0;
        for (int q = 0; q < SSZ; q++) {
            int dq = degi[q];
            r += (dq > dj) || (dq == dj && q < j);
        }
        if (r < GSZ) gsel[r] = j;
    }

    // compacted alive edges to global (tk-row-resolved)
    {
        int ptr = coffs[j];
        for (int e = st0; e < en0; e++) {
            if (alive[e]) {
                g_ein[b][ptr] = 1 + order[DENS + ein[e]];
                g_ew[b][ptr]  = ew[e];
                ptr++;
            }
        }
    }
    __syncthreads();

    for (int g = tid; g < GSZ; g += 288) {
        int jj = gsel[g];
        g_selrange[b][g][0] = coffs[jj];
        g_selrange[b][g][1] = coffs[jj] + degi[jj];
    }
    for (int u = tid; u < OUTROWS; u += 288) {
        int row;
        if (u == 0)            row = 0;
        else if (u <= DENS)    row = 1 + order[u - 1];
        else                   row = 1 + order[DENS + gsel[u - 1 - DENS]];
        g_rowmap[b][u] = row;
    }
    for (int v = tid; v < RCOLS; v += 288) {
        int c;
        if (v < DENS) c = order[v];
        else          c = order[DENS + gsel[v - DENS]];
        g_colmap[b][v] = c;
    }
}

// -------- fused output kernel: out_tokens [B,433,768] + R [B,433,432] ------
__global__ __launch_bounds__(192) void k_out(const float* __restrict__ tk,
                                             const float* __restrict__ attn,
                                             float* __restrict__ out) {
    __shared__ float srow[PTOK];
    __shared__ int   cmap[RCOLS];
    const int u = blockIdx.x;
    const int b = blockIdx.y;
    const int t = threadIdx.x;                   // 192 threads
    const int row = g_rowmap[b][u];

    // stage attention row (float4) + column map early
    const float4* a4 = (const float4*)(attn + ((size_t)b * NTOK + row) * PTOK);
    if (t < PTOK / 4) ((float4*)srow)[t] = a4[t];
    for (int v2 = t; v2 < RCOLS; v2 += 192) cmap[v2] = g_colmap[b][v2];

    // ---- tokens: one float4 per thread ----
    const float4* tk4 = (const float4*)tk;
    float4 v = tk4[((size_t)b * NTOK + row) * (DIM / 4) + t];
    if (u > DENS) {                              // aggregated skip-selected rows
        const int g = u - 1 - DENS;
        const int st = g_selrange[b][g][0];
        const int en = g_selrange[b][g][1];
        float4 acc = make_float4(0.f, 0.f, 0.f, 0.f);
        for (int e = st; e < en; e++) {          // alive-only, branch-free body
            float w  = g_ew[b][e];
            int   sr = g_ein[b][e];
            float4 sv = tk4[((size_t)b * NTOK + sr) * (DIM / 4) + t];
            acc.x += w * sv.x; acc.y += w * sv.y;
            acc.z += w * sv.z; acc.w += w * sv.w;
        }
        v.x = acc.x + v.x; v.y = acc.y + v.y;
        v.z = acc.z + v.z; v.w = acc.w + v.w;
    }
    __stcs(((float4*)out) + ((size_t)b * OUTROWS + u) * (DIM / 4) + t, v);

    // ---- R row: gather from SMEM, 16B streaming stores ----
    __syncthreads();
    float4* dst4 = (float4*)(out + (size_t)BATCH * OUTROWS * DIM
                                 + ((size_t)b * OUTROWS + u) * RCOLS);
    if (t < RCOLS / 4) {
        float4 r;
        r.x = srow[cmap[t * 4 + 0]];
        r.y = srow[cmap[t * 4 + 1]];
        r.z = srow[cmap[t * 4 + 2]];
        r.w = srow[cmap[t * 4 + 3]];
        __stcs(dst4 + t, r);
    }
}

// ---------------- launch ---------------------------------------------------
extern "C" void kernel_launch(void* const* d_in, const int* in_sizes, int n_in,
                              void* d_out, int out_size) {
    const float* tk   = (const float*)d_in[0];
    const float* attn = (const float*)d_in[1];
    float* out = (float*)d_out;

    k_order <<<dim3(4, BATCH), 192>>>(attn);
    k_top2  <<<dim3(SSZ / 8, BATCH), 256>>>(attn);
    k_graph2<<<BATCH, 288>>>(attn);
    k_out   <<<dim3(OUTROWS, BATCH), 192>>>(tk, attn, out);
}